// round 9
// baseline (speedup 1.0000x reference)
#include <cuda_runtime.h>
#include <cuda_fp16.h>
#include <cstdint>

#define MTOT 16384
#define FEMB 3072
#define FVIS 6
#define FBB  4
#define FKP  51
#define FTOT 3133
#define TDIM 256
#define KPAD 3136          // 49 * 64
#define BM 64
#define BN 64
#define BK 64
#define NSTEP (KPAD / BK)  // 49
#define A_B (BM * BK * 2)  // 8192 B
#define W_B (BN * BK * 2)  // 8192 B
#define SMEM_TOTAL (2 * A_B + 3 * W_B)  // 40 KB -> 4 CTAs/SM

__device__ int g_count;
__device__ int g_rows[MTOT];
__device__ __align__(16) __half g_Wh[TDIM * KPAD];

// ---------------------------------------------------------------- helpers
__device__ __forceinline__ uint32_t smem_u32(const void* p) {
    uint32_t a;
    asm("{ .reg .u64 t; cvta.to.shared.u64 t, %1; cvt.u32.u64 %0, t; }"
        : "=r"(a) : "l"(p));
    return a;
}

#define LDSM4(r0, r1, r2, r3, addr)                                          \
    asm volatile("ldmatrix.sync.aligned.m8n8.x4.shared.b16 {%0,%1,%2,%3}, [%4];" \
        : "=r"(r0), "=r"(r1), "=r"(r2), "=r"(r3) : "r"(addr))

#define MMA(c, a0, a1, a2, a3, b0, b1)                                       \
    asm volatile("mma.sync.aligned.m16n8k16.row.col.f32.f16.f16.f32 "        \
        "{%0,%1,%2,%3},{%4,%5,%6,%7},{%8,%9},{%0,%1,%2,%3};"                 \
        : "+f"((c)[0]), "+f"((c)[1]), "+f"((c)[2]), "+f"((c)[3])             \
        : "r"(a0), "r"(a1), "r"(a2), "r"(a3), "r"(b0), "r"(b1))

#define CP_ASYNC16(dst, src)                                                 \
    asm volatile("cp.async.cg.shared.global [%0], [%1], 16;"                 \
        :: "r"(dst), "l"(src) : "memory")
#define CP_COMMIT() asm volatile("cp.async.commit_group;" ::: "memory")
#define CP_WAIT1()  asm volatile("cp.async.wait_group 1;" ::: "memory")

__device__ __forceinline__ uint32_t h2u(__half2 v) {
    return *reinterpret_cast<uint32_t*>(&v);
}

// pack 8 floats -> 8 fp16 (one uint4)
__device__ __forceinline__ void pack8(const float* v, uint4& H) {
    __half2 h0 = __float22half2_rn(make_float2(v[0], v[1]));
    __half2 h1 = __float22half2_rn(make_float2(v[2], v[3]));
    __half2 h2 = __float22half2_rn(make_float2(v[4], v[5]));
    __half2 h3 = __float22half2_rn(make_float2(v[6], v[7]));
    H = make_uint4(h2u(h0), h2u(h1), h2u(h2), h2u(h3));
}

__device__ __forceinline__ float tail_feat(
    const float* __restrict__ vis, const float* __restrict__ bb,
    const float* __restrict__ kp, int g, int f)
{
    int d = f - FEMB;
    if (d < FVIS)              return vis[(size_t)g * FVIS + d];
    if (d < FVIS + FBB)        return bb[(size_t)g * FBB + d - FVIS];
    if (d < FVIS + FBB + FKP)  return kp[(size_t)g * FKP + d - FVIS - FBB];
    return 0.f;
}

// ---------------------------------------------------------------------------
// Kernel 1: reset counter + convert W to padded fp16
// ---------------------------------------------------------------------------
__global__ void wconv(const float* __restrict__ W) {
    if (blockIdx.x == 0 && threadIdx.x == 0) g_count = 0;
    int idx = blockIdx.x * blockDim.x + threadIdx.x;
    if (idx >= TDIM * KPAD) return;
    int n = idx / KPAD, f = idx - n * KPAD;
    float v = (f < FTOT) ? W[(size_t)n * FTOT + f] : 0.f;
    g_Wh[idx] = __float2half_rn(v);
}

// ---------------------------------------------------------------------------
// Kernel 2: compact active rows + zero inactive output rows
// ---------------------------------------------------------------------------
__global__ void compact_zero(const int* __restrict__ mask, float4* __restrict__ out) {
    int m = blockIdx.x * blockDim.x + threadIdx.x;
    bool act = (mask[m] != 0);
    unsigned bal = __ballot_sync(0xFFFFFFFFu, act);
    int lane = threadIdx.x & 31;
    int base = 0;
    if (lane == 0 && bal) base = atomicAdd(&g_count, __popc(bal));
    base = __shfl_sync(0xFFFFFFFFu, base, 0);
    if (act) {
        g_rows[base + __popc(bal & ((1u << lane) - 1u))] = m;
    } else {
        float4* o = out + (size_t)m * (TDIM / 4);
        float4 z = make_float4(0.f, 0.f, 0.f, 0.f);
#pragma unroll
        for (int i = 0; i < TDIM / 4; i++) o[i] = z;
    }
}

// ---------------------------------------------------------------------------
// Kernel 3: fp16 GEMM via mma.sync, 64x64 CTA tile, 4 warps, 4 CTAs/SM.
// Grid is (col, row): col-blocks fastest so A rows hit L2 on reuse.
// ---------------------------------------------------------------------------
__global__ __launch_bounds__(128, 4) void gemm_mma(
    const float* __restrict__ emb, const float* __restrict__ vis,
    const float* __restrict__ bb,  const float* __restrict__ kp,
    const float* __restrict__ bias, float* __restrict__ out)
{
    extern __shared__ char smem[];
    const int cnt = g_count;
    const int row0 = blockIdx.y * BM;
    if (row0 >= cnt) return;
    const int col0 = blockIdx.x * BN;

    const int tid = threadIdx.x;
    const int lane = tid & 31;
    const int wid = tid >> 5;
    const int wm = wid >> 1;      // 0..1  (32-row half)
    const int wn = wid & 1;       // 0..1  (32-col half)

    const uint32_t sbase = smem_u32(smem);
    const uint32_t sW = sbase + 2 * A_B;      // 3 W tiles follow the A buffers

    // ---- loaders: 2 threads per row, 32 features each (A and W same shape)
    const int lr = tid >> 1;                  // 0..63
    const int lh = (tid & 1) * 32;
    const int ga = g_rows[min(row0 + lr, cnt - 1)];
    const float* arow = emb + (size_t)ga * FEMB;
    const __half* wrow = g_Wh + (size_t)(col0 + lr) * KPAD;

    // swizzled 16B-chunk offsets: row stride 128B, chunk ^= (row & 7)
    uint32_t sts[4];
#pragma unroll
    for (int q = 0; q < 4; q++)
        sts[q] = (uint32_t)lr * 128 +
                 ((((uint32_t)(lh >> 3) + q) ^ (uint32_t)(lr & 7)) << 4);

    // ---- ldmatrix per-thread addressing ----
    const uint32_t lane7 = (uint32_t)(lane & 7);
    const uint32_t aRow  = (uint32_t)(wm * 32 + (lane & 15));
    const uint32_t aSel  = (uint32_t)(lane >> 4);
    const uint32_t bRow  = (uint32_t)(wn * 32 + (lane & 7) + ((lane >> 4) << 3));
    const uint32_t bSel  = (uint32_t)((lane >> 3) & 1);

    float acc[2][4][4];
#pragma unroll
    for (int i = 0; i < 2; i++)
#pragma unroll
        for (int j = 0; j < 4; j++)
#pragma unroll
            for (int q = 0; q < 4; q++) acc[i][j][q] = 0.f;

    float a[32];

    auto prefetchA = [&](int s) {
        const int f = s * BK + lh;
        if (f + 32 <= FEMB) {
            const float4* p = (const float4*)(arow + f);
#pragma unroll
            for (int q = 0; q < 8; q++) *(float4*)(a + 4 * q) = p[q];
        } else {
#pragma unroll
            for (int e = 0; e < 32; e++) a[e] = tail_feat(vis, bb, kp, ga, f + e);
        }
    };

    auto issueW = [&](int s) {
        if (s < NSTEP) {
            uint32_t base = sW + (uint32_t)(s % 3) * W_B;
            const __half* sh = wrow + s * BK + lh;
#pragma unroll
            for (int q = 0; q < 4; q++)
                CP_ASYNC16(base + sts[q], sh + 8 * q);
        }
        CP_COMMIT();
    };

    issueW(0);
    issueW(1);
    prefetchA(0);

    for (int s = 0; s < NSTEP; ++s) {
        const uint32_t ab = (uint32_t)(s & 1) * A_B;
        char* abuf = smem + ab;

        // ---- convert + store this stage's A slice (4 swizzled 16B chunks) ----
        uint4 H[4];
        pack8(a,      H[0]);
        pack8(a + 8,  H[1]);
        pack8(a + 16, H[2]);
        pack8(a + 24, H[3]);
#pragma unroll
        for (int q = 0; q < 4; q++) *(uint4*)(abuf + sts[q]) = H[q];

        CP_WAIT1();              // W(s) landed (per-thread)
        __syncthreads();         // publish A(s) + everyone's W(s); W(s-1) reads done
        issueW(s + 2);           // safe post-sync: ring slot (s+2)%3 == (s-1)%3

        if (s + 1 < NSTEP) prefetchA(s + 1);   // LDG in flight behind MMAs

        const uint32_t pA = sbase + ab;
        const uint32_t pW = sW + (uint32_t)(s % 3) * W_B;

#pragma unroll
        for (int kk = 0; kk < 4; kk++) {
            const uint32_t cA = ((uint32_t)(kk * 2) + aSel) ^ lane7;
            const uint32_t cB = ((uint32_t)(kk * 2) + bSel) ^ lane7;

            uint32_t bh[8];
            const uint32_t b0 = bRow * 128 + (cB << 4);
            LDSM4(bh[0], bh[1], bh[2], bh[3], pW + b0);
            LDSM4(bh[4], bh[5], bh[6], bh[7], pW + b0 + 16 * 128);

#pragma unroll
            for (int mt = 0; mt < 2; mt++) {
                const uint32_t aA = (aRow + mt * 16) * 128 + (cA << 4);
                uint32_t a0, a1, a2, a3;
                LDSM4(a0, a1, a2, a3, pA + aA);
#pragma unroll
                for (int nt = 0; nt < 4; nt++) {
                    MMA(acc[mt][nt], a0, a1, a2, a3, bh[2 * nt], bh[2 * nt + 1]);
                }
            }
        }
    }

    // ---------------- epilogue: bias + scatter ----------------
#pragma unroll
    for (int mt = 0; mt < 2; mt++) {
        const int mlo = wm * 32 + mt * 16 + (lane >> 2);
        const int r1 = row0 + mlo;
        const int r2 = r1 + 8;
#pragma unroll
        for (int nt = 0; nt < 4; nt++) {
            const int c = col0 + wn * 32 + nt * 8 + (lane & 3) * 2;
            const float2 bv = *(const float2*)(bias + c);
            if (r1 < cnt) {
                const int g = g_rows[r1];
                float2 o = make_float2(acc[mt][nt][0] + bv.x, acc[mt][nt][1] + bv.y);
                *(float2*)(out + (size_t)g * TDIM + c) = o;
            }
            if (r2 < cnt) {
                const int g = g_rows[r2];
                float2 o = make_float2(acc[mt][nt][2] + bv.x, acc[mt][nt][3] + bv.y);
                *(float2*)(out + (size_t)g * TDIM + c) = o;
            }
        }
    }
}

// ---------------------------------------------------------------------------
extern "C" void kernel_launch(void* const* d_in, const int* in_sizes, int n_in,
                              void* d_out, int out_size) {
    const float* emb  = (const float*)d_in[0];
    const float* vis  = (const float*)d_in[1];
    const float* bb   = (const float*)d_in[2];
    const float* kp   = (const float*)d_in[3];
    const int*   mask = (const int*)d_in[4];
    const float* W    = (const float*)d_in[5];
    const float* bias = (const float*)d_in[6];
    float*       out  = (float*)d_out;

    static bool configured = false;
    if (!configured) {
        cudaFuncSetAttribute(gemm_mma, cudaFuncAttributeMaxDynamicSharedMemorySize,
                             SMEM_TOTAL);
        configured = true;
    }

    wconv<<<(TDIM * KPAD + 255) / 256, 256>>>(W);
    compact_zero<<<MTOT / 256, 256>>>(mask, (float4*)out);
    gemm_mma<<<dim3(TDIM / BN, MTOT / BM), 128, SMEM_TOTAL>>>(
        emb, vis, bb, kp, bias, out);
}

// round 10
// speedup vs baseline: 1.1003x; 1.1003x over previous
#include <cuda_runtime.h>
#include <cuda_fp16.h>
#include <cstdint>

#define MTOT 16384
#define FEMB 3072
#define FVIS 6
#define FBB  4
#define FKP  51
#define FTOT 3133
#define TDIM 256
#define KPAD 3200          // 25 * 128
#define BM 64
#define BN 128
#define BK 128
#define NSTEP (KPAD / BK)  // 25
#define A_B (BM * BK * 2)  // 16384 B
#define W_B (BN * BK * 2)  // 32768 B
#define SMEM_TOTAL (2 * A_B + 2 * W_B)  // 96 KB -> 2 CTAs/SM

__device__ int g_count;
__device__ int g_rows[MTOT];
__device__ __align__(16) __half g_Wh[TDIM * KPAD];

// ---------------------------------------------------------------- helpers
__device__ __forceinline__ uint32_t smem_u32(const void* p) {
    uint32_t a;
    asm("{ .reg .u64 t; cvta.to.shared.u64 t, %1; cvt.u32.u64 %0, t; }"
        : "=r"(a) : "l"(p));
    return a;
}

#define LDSM4(r0, r1, r2, r3, addr)                                          \
    asm volatile("ldmatrix.sync.aligned.m8n8.x4.shared.b16 {%0,%1,%2,%3}, [%4];" \
        : "=r"(r0), "=r"(r1), "=r"(r2), "=r"(r3) : "r"(addr))

#define MMA(c, a0, a1, a2, a3, b0, b1)                                       \
    asm volatile("mma.sync.aligned.m16n8k16.row.col.f32.f16.f16.f32 "        \
        "{%0,%1,%2,%3},{%4,%5,%6,%7},{%8,%9},{%0,%1,%2,%3};"                 \
        : "+f"((c)[0]), "+f"((c)[1]), "+f"((c)[2]), "+f"((c)[3])             \
        : "r"(a0), "r"(a1), "r"(a2), "r"(a3), "r"(b0), "r"(b1))

#define CP_ASYNC16(dst, src)                                                 \
    asm volatile("cp.async.cg.shared.global [%0], [%1], 16;"                 \
        :: "r"(dst), "l"(src) : "memory")
#define CP_COMMIT() asm volatile("cp.async.commit_group;" ::: "memory")
#define CP_WAIT0()  asm volatile("cp.async.wait_group 0;" ::: "memory")

__device__ __forceinline__ uint32_t h2u(__half2 v) {
    return *reinterpret_cast<uint32_t*>(&v);
}

// pack 8 floats -> 8 fp16 (one uint4)
__device__ __forceinline__ void pack8(const float* v, uint4& H) {
    __half2 h0 = __float22half2_rn(make_float2(v[0], v[1]));
    __half2 h1 = __float22half2_rn(make_float2(v[2], v[3]));
    __half2 h2 = __float22half2_rn(make_float2(v[4], v[5]));
    __half2 h3 = __float22half2_rn(make_float2(v[6], v[7]));
    H = make_uint4(h2u(h0), h2u(h1), h2u(h2), h2u(h3));
}

// 16-chunk swizzle for 256B rows: keep chunk's 128B half, XOR low 3 bits
__device__ __forceinline__ uint32_t swz16(uint32_t c, uint32_t r7) {
    return (c & 8u) | ((c ^ r7) & 7u);
}

__device__ __forceinline__ float tail_feat(
    const float* __restrict__ vis, const float* __restrict__ bb,
    const float* __restrict__ kp, int g, int f)
{
    int d = f - FEMB;
    if (d < FVIS)              return vis[(size_t)g * FVIS + d];
    if (d < FVIS + FBB)        return bb[(size_t)g * FBB + d - FVIS];
    if (d < FVIS + FBB + FKP)  return kp[(size_t)g * FKP + d - FVIS - FBB];
    return 0.f;
}

// ---------------------------------------------------------------------------
// Kernel 1: reset counter + convert W to padded fp16
// ---------------------------------------------------------------------------
__global__ void wconv(const float* __restrict__ W) {
    if (blockIdx.x == 0 && threadIdx.x == 0) g_count = 0;
    int idx = blockIdx.x * blockDim.x + threadIdx.x;
    if (idx >= TDIM * KPAD) return;
    int n = idx / KPAD, f = idx - n * KPAD;
    float v = (f < FTOT) ? W[(size_t)n * FTOT + f] : 0.f;
    g_Wh[idx] = __float2half_rn(v);
}

// ---------------------------------------------------------------------------
// Kernel 2: compact active rows + zero inactive output rows
// ---------------------------------------------------------------------------
__global__ void compact_zero(const int* __restrict__ mask, float4* __restrict__ out) {
    int m = blockIdx.x * blockDim.x + threadIdx.x;
    bool act = (mask[m] != 0);
    unsigned bal = __ballot_sync(0xFFFFFFFFu, act);
    int lane = threadIdx.x & 31;
    int base = 0;
    if (lane == 0 && bal) base = atomicAdd(&g_count, __popc(bal));
    base = __shfl_sync(0xFFFFFFFFu, base, 0);
    if (act) {
        g_rows[base + __popc(bal & ((1u << lane) - 1u))] = m;
    } else {
        float4* o = out + (size_t)m * (TDIM / 4);
        float4 z = make_float4(0.f, 0.f, 0.f, 0.f);
#pragma unroll
        for (int i = 0; i < TDIM / 4; i++) o[i] = z;
    }
}

// ---------------------------------------------------------------------------
// Kernel 3: fp16 GEMM via mma.sync, 64x128 CTA tile, BK=128, 2 CTAs/SM.
// Grid (col, row): col-blocks fastest so paired CTAs share A rows in L2.
// ---------------------------------------------------------------------------
__global__ __launch_bounds__(256, 2) void gemm_mma(
    const float* __restrict__ emb, const float* __restrict__ vis,
    const float* __restrict__ bb,  const float* __restrict__ kp,
    const float* __restrict__ bias, float* __restrict__ out)
{
    extern __shared__ char smem[];
    const int cnt = g_count;
    const int row0 = blockIdx.y * BM;
    if (row0 >= cnt) return;
    const int col0 = blockIdx.x * BN;

    const int tid = threadIdx.x;
    const int lane = tid & 31;
    const int wid = tid >> 5;
    const int wm = wid >> 2;      // 0..1  (32-row half)
    const int wn = wid & 3;       // 0..3  (32-col quarter)

    const uint32_t sbase = smem_u32(smem);
    const uint32_t sW = sbase + 2 * A_B;      // 2 W tiles follow the A buffers

    // ---- A loader: 4 threads per row, 32 features each ----
    const int lrA = tid >> 2;                 // 0..63
    const int lhA = (tid & 3) * 32;
    const int ga = g_rows[min(row0 + lrA, cnt - 1)];
    const float* arow = emb + (size_t)ga * FEMB;
    uint32_t stsA[4];
#pragma unroll
    for (int q = 0; q < 4; q++)
        stsA[q] = (uint32_t)lrA * 256 +
                  (swz16((uint32_t)(lhA >> 3) + q, (uint32_t)(lrA & 7)) << 4);

    // ---- W loader: 2 threads per row, 64 features each ----
    const int lrW = tid >> 1;                 // 0..127
    const int lhW = (tid & 1) * 64;
    const __half* wrow = g_Wh + (size_t)(col0 + lrW) * KPAD;
    uint32_t stsW[8];
#pragma unroll
    for (int q = 0; q < 8; q++)
        stsW[q] = (uint32_t)lrW * 256 +
                  (swz16((uint32_t)(lhW >> 3) + q, (uint32_t)(lrW & 7)) << 4);

    // ---- ldmatrix per-thread addressing ----
    const uint32_t lane7 = (uint32_t)(lane & 7);
    const uint32_t aRow  = (uint32_t)(wm * 32 + (lane & 15));
    const uint32_t aSel  = (uint32_t)(lane >> 4);
    const uint32_t bRow  = (uint32_t)(wn * 32 + (lane & 7) + ((lane >> 4) << 3));
    const uint32_t bSel  = (uint32_t)((lane >> 3) & 1);

    float acc[2][4][4];
#pragma unroll
    for (int i = 0; i < 2; i++)
#pragma unroll
        for (int j = 0; j < 4; j++)
#pragma unroll
            for (int q = 0; q < 4; q++) acc[i][j][q] = 0.f;

    float a[32];

    auto prefetchA = [&](int s) {
        const int f = s * BK + lhA;
        if (f + 32 <= FEMB) {
            const float4* p = (const float4*)(arow + f);
#pragma unroll
            for (int q = 0; q < 8; q++) *(float4*)(a + 4 * q) = p[q];
        } else {
#pragma unroll
            for (int e = 0; e < 32; e++) {
                int ff = f + e;
                a[e] = (ff < FEMB) ? arow[ff] : tail_feat(vis, bb, kp, ga, ff);
            }
        }
    };

    auto issueW = [&](int s) {
        if (s < NSTEP) {
            uint32_t base = sW + (uint32_t)(s & 1) * W_B;
            const __half* sh = wrow + s * BK + lhW;
#pragma unroll
            for (int q = 0; q < 8; q++)
                CP_ASYNC16(base + stsW[q], sh + 8 * q);
        }
        CP_COMMIT();
    };

    issueW(0);
    prefetchA(0);

    for (int s = 0; s < NSTEP; ++s) {
        const uint32_t ab = (uint32_t)(s & 1) * A_B;
        char* abuf = smem + ab;

        // ---- convert + store this stage's A slice (4 swizzled 16B chunks) ----
        uint4 H[4];
        pack8(a,      H[0]);
        pack8(a + 8,  H[1]);
        pack8(a + 16, H[2]);
        pack8(a + 24, H[3]);
#pragma unroll
        for (int q = 0; q < 4; q++) *(uint4*)(abuf + stsA[q]) = H[q];

        CP_WAIT0();              // W(s) landed (only group outstanding)
        __syncthreads();         // publish A(s) + everyone's W(s); W(s-1) reads done
        issueW(s + 1);           // safe post-sync: slot (s+1)&1 held W(s-1)

        if (s + 1 < NSTEP) prefetchA(s + 1);   // LDG in flight behind MMAs

        const uint32_t pA = sbase + ab;
        const uint32_t pW = sW + (uint32_t)(s & 1) * W_B;

#pragma unroll
        for (int kk = 0; kk < 8; kk++) {
            const uint32_t cA = swz16((uint32_t)(kk * 2) + aSel, lane7);
            const uint32_t cB = swz16((uint32_t)(kk * 2) + bSel, lane7);

            uint32_t bh[8];
            const uint32_t b0 = bRow * 256 + (cB << 4);
            LDSM4(bh[0], bh[1], bh[2], bh[3], pW + b0);
            LDSM4(bh[4], bh[5], bh[6], bh[7], pW + b0 + 16 * 256);

#pragma unroll
            for (int mt = 0; mt < 2; mt++) {
                const uint32_t aA = (aRow + mt * 16) * 256 + (cA << 4);
                uint32_t a0, a1, a2, a3;
                LDSM4(a0, a1, a2, a3, pA + aA);
#pragma unroll
                for (int nt = 0; nt < 4; nt++) {
                    MMA(acc[mt][nt], a0, a1, a2, a3, bh[2 * nt], bh[2 * nt + 1]);
                }
            }
        }
    }

    // ---------------- epilogue: bias + scatter ----------------
#pragma unroll
    for (int mt = 0; mt < 2; mt++) {
        const int mlo = wm * 32 + mt * 16 + (lane >> 2);
        const int r1 = row0 + mlo;
        const int r2 = r1 + 8;
#pragma unroll
        for (int nt = 0; nt < 4; nt++) {
            const int c = col0 + wn * 32 + nt * 8 + (lane & 3) * 2;
            const float2 bv = *(const float2*)(bias + c);
            if (r1 < cnt) {
                const int g = g_rows[r1];
                float2 o = make_float2(acc[mt][nt][0] + bv.x, acc[mt][nt][1] + bv.y);
                *(float2*)(out + (size_t)g * TDIM + c) = o;
            }
            if (r2 < cnt) {
                const int g = g_rows[r2];
                float2 o = make_float2(acc[mt][nt][2] + bv.x, acc[mt][nt][3] + bv.y);
                *(float2*)(out + (size_t)g * TDIM + c) = o;
            }
        }
    }
}

// ---------------------------------------------------------------------------
extern "C" void kernel_launch(void* const* d_in, const int* in_sizes, int n_in,
                              void* d_out, int out_size) {
    const float* emb  = (const float*)d_in[0];
    const float* vis  = (const float*)d_in[1];
    const float* bb   = (const float*)d_in[2];
    const float* kp   = (const float*)d_in[3];
    const int*   mask = (const int*)d_in[4];
    const float* W    = (const float*)d_in[5];
    const float* bias = (const float*)d_in[6];
    float*       out  = (float*)d_out;

    static bool configured = false;
    if (!configured) {
        cudaFuncSetAttribute(gemm_mma, cudaFuncAttributeMaxDynamicSharedMemorySize,
                             SMEM_TOTAL);
        configured = true;
    }

    wconv<<<(TDIM * KPAD + 255) / 256, 256>>>(W);
    compact_zero<<<MTOT / 256, 256>>>(mask, (float4*)out);
    gemm_mma<<<dim3(TDIM / BN, MTOT / BM), 256, SMEM_TOTAL>>>(
        emb, vis, bb, kp, bias, out);
}

// round 11
// speedup vs baseline: 1.8037x; 1.6393x over previous
#include <cuda_runtime.h>
#include <cuda_fp16.h>
#include <cstdint>

#define MTOT 16384
#define FEMB 3072
#define FVIS 6
#define FBB  4
#define FKP  51
#define FTOT 3133
#define TDIM 256
#define KPAD 3136          // 49 * 64
#define BM 64
#define BN 128
#define BK 64
#define NSTEP (KPAD / BK)  // 49
#define A_B (BM * BK * 2)  // 8192 B
#define W_B (BN * BK * 2)  // 16384 B
#define SMEM_TOTAL (2 * A_B + 4 * W_B)  // 80 KB -> 2 CTAs/SM

__device__ int g_count;
__device__ int g_rows[MTOT];
__device__ __align__(16) __half g_Wh[TDIM * KPAD];

// ---------------------------------------------------------------- helpers
__device__ __forceinline__ uint32_t smem_u32(const void* p) {
    uint32_t a;
    asm("{ .reg .u64 t; cvta.to.shared.u64 t, %1; cvt.u32.u64 %0, t; }"
        : "=r"(a) : "l"(p));
    return a;
}

#define LDSM4(r0, r1, r2, r3, addr)                                          \
    asm volatile("ldmatrix.sync.aligned.m8n8.x4.shared.b16 {%0,%1,%2,%3}, [%4];" \
        : "=r"(r0), "=r"(r1), "=r"(r2), "=r"(r3) : "r"(addr))

#define MMA(c, a0, a1, a2, a3, b0, b1)                                       \
    asm volatile("mma.sync.aligned.m16n8k16.row.col.f32.f16.f16.f32 "        \
        "{%0,%1,%2,%3},{%4,%5,%6,%7},{%8,%9},{%0,%1,%2,%3};"                 \
        : "+f"((c)[0]), "+f"((c)[1]), "+f"((c)[2]), "+f"((c)[3])             \
        : "r"(a0), "r"(a1), "r"(a2), "r"(a3), "r"(b0), "r"(b1))

#define CP_ASYNC16(dst, src)                                                 \
    asm volatile("cp.async.cg.shared.global [%0], [%1], 16;"                 \
        :: "r"(dst), "l"(src) : "memory")
#define CP_COMMIT() asm volatile("cp.async.commit_group;" ::: "memory")
#define CP_WAIT2()  asm volatile("cp.async.wait_group 2;" ::: "memory")

__device__ __forceinline__ uint32_t h2u(__half2 v) {
    return *reinterpret_cast<uint32_t*>(&v);
}

// pack 8 floats -> 8 fp16 (one uint4)
__device__ __forceinline__ void pack8(const float* v, uint4& H) {
    __half2 h0 = __float22half2_rn(make_float2(v[0], v[1]));
    __half2 h1 = __float22half2_rn(make_float2(v[2], v[3]));
    __half2 h2 = __float22half2_rn(make_float2(v[4], v[5]));
    __half2 h3 = __float22half2_rn(make_float2(v[6], v[7]));
    H = make_uint4(h2u(h0), h2u(h1), h2u(h2), h2u(h3));
}

__device__ __forceinline__ float tail_feat(
    const float* __restrict__ vis, const float* __restrict__ bb,
    const float* __restrict__ kp, int g, int f)
{
    int d = f - FEMB;
    if (d < FVIS)              return vis[(size_t)g * FVIS + d];
    if (d < FVIS + FBB)        return bb[(size_t)g * FBB + d - FVIS];
    if (d < FVIS + FBB + FKP)  return kp[(size_t)g * FKP + d - FVIS - FBB];
    return 0.f;
}

// ---------------------------------------------------------------------------
// Kernel 1: reset counter + convert W to padded fp16
// ---------------------------------------------------------------------------
__global__ void wconv(const float* __restrict__ W) {
    if (blockIdx.x == 0 && threadIdx.x == 0) g_count = 0;
    int idx = blockIdx.x * blockDim.x + threadIdx.x;
    if (idx >= TDIM * KPAD) return;
    int n = idx / KPAD, f = idx - n * KPAD;
    float v = (f < FTOT) ? W[(size_t)n * FTOT + f] : 0.f;
    g_Wh[idx] = __float2half_rn(v);
}

// ---------------------------------------------------------------------------
// Kernel 2: compact active rows + zero inactive output rows
// ---------------------------------------------------------------------------
__global__ void compact_zero(const int* __restrict__ mask, float4* __restrict__ out) {
    int m = blockIdx.x * blockDim.x + threadIdx.x;
    bool act = (mask[m] != 0);
    unsigned bal = __ballot_sync(0xFFFFFFFFu, act);
    int lane = threadIdx.x & 31;
    int base = 0;
    if (lane == 0 && bal) base = atomicAdd(&g_count, __popc(bal));
    base = __shfl_sync(0xFFFFFFFFu, base, 0);
    if (act) {
        g_rows[base + __popc(bal & ((1u << lane) - 1u))] = m;
    } else {
        float4* o = out + (size_t)m * (TDIM / 4);
        float4 z = make_float4(0.f, 0.f, 0.f, 0.f);
#pragma unroll
        for (int i = 0; i < TDIM / 4; i++) o[i] = z;
    }
}

// ---------------------------------------------------------------------------
// Kernel 3: fp16 GEMM via mma.sync, 64x128 CTA tile, 2 CTAs/SM.
// Grid (col, row): col-blocks fastest so paired CTAs share A rows via L2.
// ---------------------------------------------------------------------------
__global__ __launch_bounds__(256, 2) void gemm_mma(
    const float* __restrict__ emb, const float* __restrict__ vis,
    const float* __restrict__ bb,  const float* __restrict__ kp,
    const float* __restrict__ bias, float* __restrict__ out)
{
    extern __shared__ char smem[];
    const int cnt = g_count;
    const int row0 = blockIdx.y * BM;
    if (row0 >= cnt) return;
    const int col0 = blockIdx.x * BN;

    const int tid = threadIdx.x;
    const int lane = tid & 31;
    const int wid = tid >> 5;
    const int wm = wid >> 2;      // 0..1  (32-row half)
    const int wn = wid & 3;       // 0..3  (32-col quarter)

    const uint32_t sbase = smem_u32(smem);
    const uint32_t sW = sbase + 2 * A_B;      // 4 W tiles follow the A buffers

    // ---- A loader: 4 threads per row, 16 features each ----
    const int lrA = tid >> 2;                 // 0..63
    const int lhA = (tid & 3) * 16;
    const int ga = g_rows[min(row0 + lrA, cnt - 1)];
    const float* arow = emb + (size_t)ga * FEMB;
    uint32_t stsA[2];
#pragma unroll
    for (int q = 0; q < 2; q++)
        stsA[q] = (uint32_t)lrA * 128 +
                  ((((uint32_t)(lhA >> 3) + q) ^ (uint32_t)(lrA & 7)) << 4);

    // ---- W loader: 2 threads per row, 32 features each ----
    const int lrW = tid >> 1;                 // 0..127
    const int lhW = (tid & 1) * 32;
    const __half* wrow = g_Wh + (size_t)(col0 + lrW) * KPAD;
    uint32_t stsW[4];
#pragma unroll
    for (int q = 0; q < 4; q++)
        stsW[q] = (uint32_t)lrW * 128 +
                  ((((uint32_t)(lhW >> 3) + q) ^ (uint32_t)(lrW & 7)) << 4);

    // ---- ldmatrix per-thread addressing ----
    const uint32_t lane7 = (uint32_t)(lane & 7);
    const uint32_t aRow  = (uint32_t)(wm * 32 + (lane & 15));
    const uint32_t aSel  = (uint32_t)(lane >> 4);
    const uint32_t bRow  = (uint32_t)(wn * 32 + (lane & 7) + ((lane >> 4) << 3));
    const uint32_t bSel  = (uint32_t)((lane >> 3) & 1);

    float acc[2][4][4];
#pragma unroll
    for (int i = 0; i < 2; i++)
#pragma unroll
        for (int j = 0; j < 4; j++)
#pragma unroll
            for (int q = 0; q < 4; q++) acc[i][j][q] = 0.f;

    float a[16];

    auto prefetchA = [&](int s) {
        const int f = s * BK + lhA;
        if (f + 16 <= FEMB) {
            const float4* p = (const float4*)(arow + f);
#pragma unroll
            for (int q = 0; q < 4; q++) *(float4*)(a + 4 * q) = p[q];
        } else {
#pragma unroll
            for (int e = 0; e < 16; e++) {
                int ff = f + e;
                a[e] = (ff < FEMB) ? arow[ff] : tail_feat(vis, bb, kp, ga, ff);
            }
        }
    };

    auto issueW = [&](int s) {
        if (s < NSTEP) {
            uint32_t base = sW + (uint32_t)(s & 3) * W_B;
            const __half* sh = wrow + s * BK + lhW;
#pragma unroll
            for (int q = 0; q < 4; q++)
                CP_ASYNC16(base + stsW[q], sh + 8 * q);
        }
        CP_COMMIT();
    };

    issueW(0);
    issueW(1);
    prefetchA(0);

    for (int s = 0; s < NSTEP; ++s) {
        const uint32_t ab = (uint32_t)(s & 1) * A_B;
        char* abuf = smem + ab;

        // ---- convert + store this stage's A slice (2 swizzled 16B chunks) ----
        uint4 H[2];
        pack8(a,     H[0]);
        pack8(a + 8, H[1]);
#pragma unroll
        for (int q = 0; q < 2; q++) *(uint4*)(abuf + stsA[q]) = H[q];

        issueW(s + 2);
        CP_WAIT2();              // W(s) landed (per-thread)
        __syncthreads();         // publish A(s) stores + everyone's W(s)

        if (s + 1 < NSTEP) prefetchA(s + 1);   // LDG in flight behind MMAs

        const uint32_t pA = sbase + ab;
        const uint32_t pW = sW + (uint32_t)(s & 3) * W_B;

#pragma unroll
        for (int kk = 0; kk < 4; kk++) {
            const uint32_t cA = ((uint32_t)(kk * 2) + aSel) ^ lane7;
            const uint32_t cB = ((uint32_t)(kk * 2) + bSel) ^ lane7;

            uint32_t bh[8];
            const uint32_t b0 = bRow * 128 + (cB << 4);
            LDSM4(bh[0], bh[1], bh[2], bh[3], pW + b0);
            LDSM4(bh[4], bh[5], bh[6], bh[7], pW + b0 + 16 * 128);

#pragma unroll
            for (int mt = 0; mt < 2; mt++) {
                const uint32_t aA = (aRow + mt * 16) * 128 + (cA << 4);
                uint32_t a0, a1, a2, a3;
                LDSM4(a0, a1, a2, a3, pA + aA);
#pragma unroll
                for (int nt = 0; nt < 4; nt++) {
                    MMA(acc[mt][nt], a0, a1, a2, a3, bh[2 * nt], bh[2 * nt + 1]);
                }
            }
        }
    }

    // ---------------- epilogue: bias + scatter ----------------
#pragma unroll
    for (int mt = 0; mt < 2; mt++) {
        const int mlo = wm * 32 + mt * 16 + (lane >> 2);
        const int r1 = row0 + mlo;
        const int r2 = r1 + 8;
#pragma unroll
        for (int nt = 0; nt < 4; nt++) {
            const int c = col0 + wn * 32 + nt * 8 + (lane & 3) * 2;
            const float2 bv = *(const float2*)(bias + c);
            if (r1 < cnt) {
                const int g = g_rows[r1];
                float2 o = make_float2(acc[mt][nt][0] + bv.x, acc[mt][nt][1] + bv.y);
                *(float2*)(out + (size_t)g * TDIM + c) = o;
            }
            if (r2 < cnt) {
                const int g = g_rows[r2];
                float2 o = make_float2(acc[mt][nt][2] + bv.x, acc[mt][nt][3] + bv.y);
                *(float2*)(out + (size_t)g * TDIM + c) = o;
            }
        }
    }
}

// ---------------------------------------------------------------------------
extern "C" void kernel_launch(void* const* d_in, const int* in_sizes, int n_in,
                              void* d_out, int out_size) {
    const float* emb  = (const float*)d_in[0];
    const float* vis  = (const float*)d_in[1];
    const float* bb   = (const float*)d_in[2];
    const float* kp   = (const float*)d_in[3];
    const int*   mask = (const int*)d_in[4];
    const float* W    = (const float*)d_in[5];
    const float* bias = (const float*)d_in[6];
    float*       out  = (float*)d_out;

    static bool configured = false;
    if (!configured) {
        cudaFuncSetAttribute(gemm_mma, cudaFuncAttributeMaxDynamicSharedMemorySize,
                             SMEM_TOTAL);
        configured = true;
    }

    wconv<<<(TDIM * KPAD + 255) / 256, 256>>>(W);
    compact_zero<<<MTOT / 256, 256>>>(mask, (float4*)out);
    gemm_mma<<<dim3(TDIM / BN, MTOT / BM), 256, SMEM_TOTAL>>>(
        emb, vis, bb, kp, bias, out);
}